// round 4
// baseline (speedup 1.0000x reference)
#include <cuda_runtime.h>
#include <math.h>
#include <stdint.h>

// Problem-fixed sizes: N=100000, E=3200000, NF=16, H=32, HO=64
#define NMAX 100000
#define NF 16
#define H  32
#define HO 64

__device__ float  g_agg[NMAX * NF];   // scatter-sum accumulator (zeroed in k_pre)
__device__ float  g_h1 [NMAX * H];
__device__ float  g_h2 [NMAX * H];
__device__ double g_s1 [2 * H];       // sum[32], sumsq[32]
__device__ double g_s2 [2 * H];
__device__ int    g_is64;

__device__ __forceinline__ float gelu_exact(float v) {
    return 0.5f * v * (1.0f + erff(v * 0.70710678118654752f));
}

// ---------------------------------------------------------------------------
// K0: zero g_agg + stats accumulators; detect edge_index dtype
// ---------------------------------------------------------------------------
__global__ __launch_bounds__(256) void k_pre(const int* __restrict__ eidx32,
                                             int n4 /* N*NF/4 */) {
    int i = blockIdx.x * blockDim.x + threadIdx.x;
    if (i < n4) ((float4*)g_agg)[i] = make_float4(0.f, 0.f, 0.f, 0.f);
    if (blockIdx.x == 0) {
        if (threadIdx.x < 2 * H)       g_s1[threadIdx.x]         = 0.0;
        else if (threadIdx.x < 4 * H)  g_s2[threadIdx.x - 2 * H] = 0.0;
        if (threadIdx.x == 0) {
            int nz = 0;
            #pragma unroll
            for (int k = 0; k < 64; k++) nz |= eidx32[2 * k + 1];
            g_is64 = (nz == 0) ? 1 : 0;
        }
    }
}

// ---------------------------------------------------------------------------
// K1-K3: edge slice, 4 THREADS PER EDGE. Lane group c = tid&3 handles
// features [4c, 4c+4). One LDG.128 gather + one RED.128 scatter per thread;
// 4 lanes of a group share a 64B row segment -> coalesced L1 wavefronts.
// ---------------------------------------------------------------------------
__global__ __launch_bounds__(256) void k_edge(const float* __restrict__ x,
                                              const void*  __restrict__ eidx,
                                              const float* __restrict__ ea,
                                              const float* __restrict__ We,
                                              const float* __restrict__ be,
                                              int eLo, int eHi, int E) {
    // Weights transposed per chunk: sW[c][k][4] = We[k][4c..4c+4)
    __shared__ float sW[4][8][4];
    __shared__ float sb[16];
    __shared__ int   sIs64;
    int t = threadIdx.x;
    if (t < 128) {
        int k = t >> 4, j = t & 15;      // We row-major [8][16]
        sW[j >> 2][k][j & 3] = We[t];
    }
    if (t < 16) sb[t] = be[t];
    if (t == 0) sIs64 = g_is64;
    __syncthreads();

    int gt = blockIdx.x * blockDim.x + t;
    int e  = eLo + (gt >> 2);
    if (e >= eHi) return;
    int c  = gt & 3;

    int src, dst;
    if (sIs64) {
        src = ((const int2*)eidx)[e].x;
        dst = ((const int2*)eidx)[e + E].x;
    } else {
        const int* p32 = (const int*)eidx;
        src = p32[e]; dst = p32[e + E];
    }

    const float4* ear = (const float4*)(ea + (size_t)e * 8);
    float4 a0 = __ldg(ear);
    float4 a1 = __ldg(ear + 1);
    float av[8] = {a0.x, a0.y, a0.z, a0.w, a1.x, a1.y, a1.z, a1.w};

    float m0 = sb[4*c+0], m1 = sb[4*c+1], m2 = sb[4*c+2], m3 = sb[4*c+3];
    #pragma unroll
    for (int k = 0; k < 8; k++) {
        m0 = fmaf(av[k], sW[c][k][0], m0);
        m1 = fmaf(av[k], sW[c][k][1], m1);
        m2 = fmaf(av[k], sW[c][k][2], m2);
        m3 = fmaf(av[k], sW[c][k][3], m3);
    }

    float4 xv = __ldg((const float4*)(x + (size_t)src * 16) + c);
    float4 r;
    r.x = fmaxf(xv.x + m0, 0.0f);
    r.y = fmaxf(xv.y + m1, 0.0f);
    r.z = fmaxf(xv.z + m2, 0.0f);
    r.w = fmaxf(xv.w + m3, 0.0f);
    atomicAdd((float4*)(g_agg + (size_t)dst * 16) + c, r);
}

// ---------------------------------------------------------------------------
// stats epilogue: smem transpose (conflict-free), then double atomics
// ---------------------------------------------------------------------------
__device__ __forceinline__ void stats_epilogue(const float* acc, bool valid,
                                               double* sums) {
    __shared__ float tr[8][32][33];
    __shared__ float shs[8][32], shq[8][32];
    int lane = threadIdx.x & 31;
    int wid  = threadIdx.x >> 5;
    #pragma unroll
    for (int j = 0; j < H; j++) tr[wid][j][lane] = valid ? acc[j] : 0.0f;
    __syncwarp();
    float s = 0.0f, q = 0.0f;
    #pragma unroll
    for (int k = 0; k < 32; k++) {
        float v = tr[wid][lane][k];
        s += v; q = fmaf(v, v, q);
    }
    shs[wid][lane] = s; shq[wid][lane] = q;
    __syncthreads();
    if (wid == 0) {
        float ts = 0.0f, tq = 0.0f;
        #pragma unroll
        for (int w = 0; w < 8; w++) { ts += shs[w][lane]; tq += shq[w][lane]; }
        atomicAdd(&sums[lane],     (double)ts);
        atomicAdd(&sums[H + lane], (double)tq);
    }
}

// ---------------------------------------------------------------------------
// BN finalize inline (per-block, threads 0..31 write smem scale/shift)
// ---------------------------------------------------------------------------
__device__ __forceinline__ void fin_inline(const double* __restrict__ sums,
                                           const float* __restrict__ gamma,
                                           const float* __restrict__ beta,
                                           int N, float* ssc, float* ssh) {
    if (threadIdx.x < H) {
        int f = threadIdx.x;
        double mean = sums[f] / (double)N;
        double var  = sums[H + f] / (double)N - mean * mean;
        double inv  = 1.0 / sqrt(var + 1e-5);
        ssc[f] = (float)((double)gamma[f] * inv);
        ssh[f] = (float)((double)beta[f] - mean * (double)gamma[f] * inv);
    }
}

// ---------------------------------------------------------------------------
// K4: h1 = ((1+eps)*x + agg) @ W1 + b1   (+ fused BN1 stats)
// ---------------------------------------------------------------------------
__global__ __launch_bounds__(256) void k_gemm1(const float* __restrict__ x,
                                               const float* __restrict__ epsp,
                                               const float* __restrict__ W1,
                                               const float* __restrict__ b1,
                                               int N) {
    __shared__ float sW[NF * H];
    __shared__ float sb[H];
    for (int i = threadIdx.x; i < NF * H; i += blockDim.x) sW[i] = W1[i];
    if (threadIdx.x < H) sb[threadIdx.x] = b1[threadIdx.x];
    __syncthreads();

    int n = blockIdx.x * blockDim.x + threadIdx.x;
    bool valid = n < N;
    float sc = 1.0f + epsp[0];

    float a[NF];
    #pragma unroll
    for (int k = 0; k < NF; k++) a[k] = 0.0f;
    if (valid) {
        const float4* ar = (const float4*)(g_agg + (size_t)n * NF);
        const float4* xr = (const float4*)(x     + (size_t)n * NF);
        #pragma unroll
        for (int c = 0; c < 4; c++) {
            float4 v = ar[c];
            float4 xv = xr[c];
            a[4*c+0] = fmaf(sc, xv.x, v.x);
            a[4*c+1] = fmaf(sc, xv.y, v.y);
            a[4*c+2] = fmaf(sc, xv.z, v.z);
            a[4*c+3] = fmaf(sc, xv.w, v.w);
        }
    }
    float acc[H];
    #pragma unroll
    for (int j = 0; j < H; j++) acc[j] = sb[j];
    #pragma unroll
    for (int k = 0; k < NF; k++)
        #pragma unroll
        for (int j = 0; j < H; j++) acc[j] = fmaf(a[k], sW[k * H + j], acc[j]);

    if (valid) {
        float4* hr = (float4*)(g_h1 + (size_t)n * H);
        #pragma unroll
        for (int c = 0; c < H / 4; c++)
            hr[c] = make_float4(acc[4*c], acc[4*c+1], acc[4*c+2], acc[4*c+3]);
    }
    stats_epilogue(acc, valid, g_s1);
}

// ---------------------------------------------------------------------------
// K5: h2 = gelu(bn1(h1)) @ W2 + b2   (BN1 finalize inline, + fused BN2 stats)
// ---------------------------------------------------------------------------
__global__ __launch_bounds__(256) void k_gemm2(const float* __restrict__ g1,
                                               const float* __restrict__ bt1,
                                               const float* __restrict__ W2,
                                               const float* __restrict__ b2,
                                               int N) {
    __shared__ float sW[H * H];
    __shared__ float sb[H], ssc[H], ssh[H];
    for (int i = threadIdx.x; i < H * H; i += blockDim.x) sW[i] = W2[i];
    if (threadIdx.x < H) sb[threadIdx.x] = b2[threadIdx.x];
    fin_inline(g_s1, g1, bt1, N, ssc, ssh);
    __syncthreads();

    int n = blockIdx.x * blockDim.x + threadIdx.x;
    bool valid = n < N;

    float y[H];
    #pragma unroll
    for (int j = 0; j < H; j++) y[j] = 0.0f;
    if (valid) {
        const float4* hr = (const float4*)(g_h1 + (size_t)n * H);
        #pragma unroll
        for (int c = 0; c < H / 4; c++) {
            float4 v = hr[c];
            y[4*c+0] = gelu_exact(fmaf(v.x, ssc[4*c+0], ssh[4*c+0]));
            y[4*c+1] = gelu_exact(fmaf(v.y, ssc[4*c+1], ssh[4*c+1]));
            y[4*c+2] = gelu_exact(fmaf(v.z, ssc[4*c+2], ssh[4*c+2]));
            y[4*c+3] = gelu_exact(fmaf(v.w, ssc[4*c+3], ssh[4*c+3]));
        }
    }
    float acc[H];
    #pragma unroll
    for (int j = 0; j < H; j++) acc[j] = sb[j];
    #pragma unroll
    for (int k = 0; k < H; k++)
        #pragma unroll
        for (int j = 0; j < H; j++) acc[j] = fmaf(y[k], sW[k * H + j], acc[j]);

    if (valid) {
        float4* o = (float4*)(g_h2 + (size_t)n * H);
        #pragma unroll
        for (int c = 0; c < H / 4; c++)
            o[c] = make_float4(acc[4*c], acc[4*c+1], acc[4*c+2], acc[4*c+3]);
    }
    stats_epilogue(acc, valid, g_s2);
}

// ---------------------------------------------------------------------------
// K6: out = gelu(bn2(h2)) @ W3 + b3   (BN2 finalize inline)
// ---------------------------------------------------------------------------
__global__ __launch_bounds__(256) void k_out(const float* __restrict__ g2,
                                             const float* __restrict__ bt2,
                                             const float* __restrict__ W3,
                                             const float* __restrict__ b3,
                                             float* __restrict__ out,
                                             int N) {
    __shared__ float sW[H * HO];
    __shared__ float sb[HO], ssc[H], ssh[H];
    for (int i = threadIdx.x; i < H * HO; i += blockDim.x) sW[i] = W3[i];
    if (threadIdx.x < HO) sb[threadIdx.x] = b3[threadIdx.x];
    fin_inline(g_s2, g2, bt2, N, ssc, ssh);
    __syncthreads();

    int n = blockIdx.x * blockDim.x + threadIdx.x;
    if (n >= N) return;

    float y[H];
    const float4* hr = (const float4*)(g_h2 + (size_t)n * H);
    #pragma unroll
    for (int c = 0; c < H / 4; c++) {
        float4 v = hr[c];
        y[4*c+0] = gelu_exact(fmaf(v.x, ssc[4*c+0], ssh[4*c+0]));
        y[4*c+1] = gelu_exact(fmaf(v.y, ssc[4*c+1], ssh[4*c+1]));
        y[4*c+2] = gelu_exact(fmaf(v.z, ssc[4*c+2], ssh[4*c+2]));
        y[4*c+3] = gelu_exact(fmaf(v.w, ssc[4*c+3], ssh[4*c+3]));
    }

    float4* orow = (float4*)(out + (size_t)n * HO);
    #pragma unroll
    for (int jb = 0; jb < HO; jb += 32) {
        float acc[32];
        #pragma unroll
        for (int j = 0; j < 32; j++) acc[j] = sb[jb + j];
        #pragma unroll
        for (int k = 0; k < H; k++)
            #pragma unroll
            for (int j = 0; j < 32; j++) acc[j] = fmaf(y[k], sW[k * HO + jb + j], acc[j]);
        #pragma unroll
        for (int c = 0; c < 8; c++)
            orow[jb / 4 + c] = make_float4(acc[4*c], acc[4*c+1], acc[4*c+2], acc[4*c+3]);
    }
}

// ---------------------------------------------------------------------------
extern "C" void kernel_launch(void* const* d_in, const int* in_sizes, int n_in,
                              void* d_out, int out_size) {
    const float* x    = (const float*)d_in[0];
    const void*  eidx =               d_in[1];
    const float* ea   = (const float*)d_in[2];
    const float* We   = (const float*)d_in[3];
    const float* be   = (const float*)d_in[4];
    const float* W1   = (const float*)d_in[5];
    const float* b1   = (const float*)d_in[6];
    const float* g1   = (const float*)d_in[7];
    const float* bt1  = (const float*)d_in[8];
    const float* W2   = (const float*)d_in[9];
    const float* b2   = (const float*)d_in[10];
    const float* epsp = (const float*)d_in[11];
    const float* g2   = (const float*)d_in[12];
    const float* bt2  = (const float*)d_in[13];
    const float* W3   = (const float*)d_in[14];
    const float* b3   = (const float*)d_in[15];
    float* out = (float*)d_out;

    int N = in_sizes[0] / NF;
    int E = in_sizes[2] / 8;
    int n4 = N * NF / 4;
    int nb = (N + 255) / 256;

    int e1 = E / 3, e2 = 2 * (E / 3);

    k_pre  <<<(n4 + 255) / 256, 256>>>((const int*)eidx, n4);
    // 4 threads per edge
    k_edge <<<((e1) * 4 + 255) / 256, 256>>>(x, eidx, ea, We, be, 0, e1, E);
    k_edge <<<((e2 - e1) * 4 + 255) / 256, 256>>>(x, eidx, ea, We, be, e1, e2, E);
    k_edge <<<((E - e2) * 4 + 255) / 256, 256>>>(x, eidx, ea, We, be, e2, E, E);  // profiled
    k_gemm1<<<nb, 256>>>(x, epsp, W1, b1, N);
    k_gemm2<<<nb, 256>>>(g1, bt1, W2, b2, N);
    k_out  <<<nb, 256>>>(g2, bt2, W3, b3, out, N);
}

// round 5
// speedup vs baseline: 1.5752x; 1.5752x over previous
#include <cuda_runtime.h>
#include <math.h>
#include <stdint.h>

// Problem-fixed sizes: N=100000, E=3200000, NF=16, H=32, HO=64
#define NMAX 100000
#define NF 16
#define H  32
#define HO 64

__device__ float  g_agg[NMAX * NF];   // scatter-sum accumulator (zeroed in k_pre)
__device__ float  g_h1 [NMAX * H];
__device__ float  g_h2 [NMAX * H];
__device__ double g_s1 [2 * H];       // sum[32], sumsq[32]
__device__ double g_s2 [2 * H];
__device__ int    g_is64;

__device__ __forceinline__ float gelu_exact(float v) {
    return 0.5f * v * (1.0f + erff(v * 0.70710678118654752f));
}

// ---------------------------------------------------------------------------
// K0: zero g_agg + stats accumulators; detect edge_index dtype
// ---------------------------------------------------------------------------
__global__ __launch_bounds__(256) void k_pre(const int* __restrict__ eidx32,
                                             int n4 /* N*NF/4 */) {
    int i = blockIdx.x * blockDim.x + threadIdx.x;
    if (i < n4) ((float4*)g_agg)[i] = make_float4(0.f, 0.f, 0.f, 0.f);
    if (blockIdx.x == 0) {
        if (threadIdx.x < 2 * H)       g_s1[threadIdx.x]         = 0.0;
        else if (threadIdx.x < 4 * H)  g_s2[threadIdx.x - 2 * H] = 0.0;
        if (threadIdx.x == 0) {
            int nz = 0;
            #pragma unroll
            for (int k = 0; k < 64; k++) nz |= eidx32[2 * k + 1];
            g_is64 = (nz == 0) ? 1 : 0;
        }
    }
}

// ---------------------------------------------------------------------------
// K1-K3: edge slice, 4 threads per edge; lane group c = tid&3 handles
// features [4c, 4c+4). One LDG.128 gather + one RED.128 scatter per thread.
// Weight tile padded to [4][9][4] so the 4 lane groups hit 4 distinct banks
// (row stride 36 floats: bank = (4c + 4k + r) % 32) and chunks stay
// 16B-aligned for LDS.128.
// ---------------------------------------------------------------------------
__global__ __launch_bounds__(256) void k_edge(const float* __restrict__ x,
                                              const void*  __restrict__ eidx,
                                              const float* __restrict__ ea,
                                              const float* __restrict__ We,
                                              const float* __restrict__ be,
                                              int eLo, int eHi, int E) {
    __shared__ float sW[4][9][4];   // padded: stride 36 floats per c-row
    __shared__ float sb[16];
    __shared__ int   sIs64;
    int t = threadIdx.x;
    if (t < 128) {
        int k = t >> 4, j = t & 15;      // We row-major [8][16]
        sW[j >> 2][k][j & 3] = We[t];
    }
    if (t < 16) sb[t] = be[t];
    if (t == 0) sIs64 = g_is64;
    __syncthreads();

    int gt = blockIdx.x * blockDim.x + t;
    int e  = eLo + (gt >> 2);
    if (e >= eHi) return;
    int c  = gt & 3;

    int src, dst;
    if (sIs64) {
        src = ((const int2*)eidx)[e].x;
        dst = ((const int2*)eidx)[e + E].x;
    } else {
        const int* p32 = (const int*)eidx;
        src = p32[e]; dst = p32[e + E];
    }

    const float4* ear = (const float4*)(ea + (size_t)e * 8);
    float4 a0 = __ldg(ear);
    float4 a1 = __ldg(ear + 1);
    float av[8] = {a0.x, a0.y, a0.z, a0.w, a1.x, a1.y, a1.z, a1.w};

    float m0 = sb[4*c+0], m1 = sb[4*c+1], m2 = sb[4*c+2], m3 = sb[4*c+3];
    #pragma unroll
    for (int k = 0; k < 8; k++) {
        m0 = fmaf(av[k], sW[c][k][0], m0);
        m1 = fmaf(av[k], sW[c][k][1], m1);
        m2 = fmaf(av[k], sW[c][k][2], m2);
        m3 = fmaf(av[k], sW[c][k][3], m3);
    }

    float4 xv = __ldg((const float4*)(x + (size_t)src * 16) + c);
    float4 r;
    r.x = fmaxf(xv.x + m0, 0.0f);
    r.y = fmaxf(xv.y + m1, 0.0f);
    r.z = fmaxf(xv.z + m2, 0.0f);
    r.w = fmaxf(xv.w + m3, 0.0f);
    atomicAdd((float4*)(g_agg + (size_t)dst * 16) + c, r);
}

// ---------------------------------------------------------------------------
// stats epilogue: smem transpose (conflict-free), then double atomics
// ---------------------------------------------------------------------------
__device__ __forceinline__ void stats_epilogue(const float* acc, bool valid,
                                               double* sums) {
    __shared__ float tr[8][32][33];
    __shared__ float shs[8][32], shq[8][32];
    int lane = threadIdx.x & 31;
    int wid  = threadIdx.x >> 5;
    #pragma unroll
    for (int j = 0; j < H; j++) tr[wid][j][lane] = valid ? acc[j] : 0.0f;
    __syncwarp();
    float s = 0.0f, q = 0.0f;
    #pragma unroll
    for (int k = 0; k < 32; k++) {
        float v = tr[wid][lane][k];
        s += v; q = fmaf(v, v, q);
    }
    shs[wid][lane] = s; shq[wid][lane] = q;
    __syncthreads();
    if (wid == 0) {
        float ts = 0.0f, tq = 0.0f;
        #pragma unroll
        for (int w = 0; w < 8; w++) { ts += shs[w][lane]; tq += shq[w][lane]; }
        atomicAdd(&sums[lane],     (double)ts);
        atomicAdd(&sums[H + lane], (double)tq);
    }
}

// ---------------------------------------------------------------------------
// BN finalize inline (per-block, threads 0..31 write smem scale/shift)
// ---------------------------------------------------------------------------
__device__ __forceinline__ void fin_inline(const double* __restrict__ sums,
                                           const float* __restrict__ gamma,
                                           const float* __restrict__ beta,
                                           int N, float* ssc, float* ssh) {
    if (threadIdx.x < H) {
        int f = threadIdx.x;
        double mean = sums[f] / (double)N;
        double var  = sums[H + f] / (double)N - mean * mean;
        double inv  = 1.0 / sqrt(var + 1e-5);
        ssc[f] = (float)((double)gamma[f] * inv);
        ssh[f] = (float)((double)beta[f] - mean * (double)gamma[f] * inv);
    }
}

// ---------------------------------------------------------------------------
// K4: h1 = ((1+eps)*x + agg) @ W1 + b1   (+ fused BN1 stats)
// ---------------------------------------------------------------------------
__global__ __launch_bounds__(256) void k_gemm1(const float* __restrict__ x,
                                               const float* __restrict__ epsp,
                                               const float* __restrict__ W1,
                                               const float* __restrict__ b1,
                                               int N) {
    __shared__ float sW[NF * H];
    __shared__ float sb[H];
    for (int i = threadIdx.x; i < NF * H; i += blockDim.x) sW[i] = W1[i];
    if (threadIdx.x < H) sb[threadIdx.x] = b1[threadIdx.x];
    __syncthreads();

    int n = blockIdx.x * blockDim.x + threadIdx.x;
    bool valid = n < N;
    float sc = 1.0f + epsp[0];

    float a[NF];
    #pragma unroll
    for (int k = 0; k < NF; k++) a[k] = 0.0f;
    if (valid) {
        const float4* ar = (const float4*)(g_agg + (size_t)n * NF);
        const float4* xr = (const float4*)(x     + (size_t)n * NF);
        #pragma unroll
        for (int c = 0; c < 4; c++) {
            float4 v = ar[c];
            float4 xv = xr[c];
            a[4*c+0] = fmaf(sc, xv.x, v.x);
            a[4*c+1] = fmaf(sc, xv.y, v.y);
            a[4*c+2] = fmaf(sc, xv.z, v.z);
            a[4*c+3] = fmaf(sc, xv.w, v.w);
        }
    }
    float acc[H];
    #pragma unroll
    for (int j = 0; j < H; j++) acc[j] = sb[j];
    #pragma unroll
    for (int k = 0; k < NF; k++)
        #pragma unroll
        for (int j = 0; j < H; j++) acc[j] = fmaf(a[k], sW[k * H + j], acc[j]);

    if (valid) {
        float4* hr = (float4*)(g_h1 + (size_t)n * H);
        #pragma unroll
        for (int c = 0; c < H / 4; c++)
            hr[c] = make_float4(acc[4*c], acc[4*c+1], acc[4*c+2], acc[4*c+3]);
    }
    stats_epilogue(acc, valid, g_s1);
}

// ---------------------------------------------------------------------------
// K5: h2 = gelu(bn1(h1)) @ W2 + b2   (BN1 finalize inline, + fused BN2 stats)
// ---------------------------------------------------------------------------
__global__ __launch_bounds__(256) void k_gemm2(const float* __restrict__ g1,
                                               const float* __restrict__ bt1,
                                               const float* __restrict__ W2,
                                               const float* __restrict__ b2,
                                               int N) {
    __shared__ float sW[H * H];
    __shared__ float sb[H], ssc[H], ssh[H];
    for (int i = threadIdx.x; i < H * H; i += blockDim.x) sW[i] = W2[i];
    if (threadIdx.x < H) sb[threadIdx.x] = b2[threadIdx.x];
    fin_inline(g_s1, g1, bt1, N, ssc, ssh);
    __syncthreads();

    int n = blockIdx.x * blockDim.x + threadIdx.x;
    bool valid = n < N;

    float y[H];
    #pragma unroll
    for (int j = 0; j < H; j++) y[j] = 0.0f;
    if (valid) {
        const float4* hr = (const float4*)(g_h1 + (size_t)n * H);
        #pragma unroll
        for (int c = 0; c < H / 4; c++) {
            float4 v = hr[c];
            y[4*c+0] = gelu_exact(fmaf(v.x, ssc[4*c+0], ssh[4*c+0]));
            y[4*c+1] = gelu_exact(fmaf(v.y, ssc[4*c+1], ssh[4*c+1]));
            y[4*c+2] = gelu_exact(fmaf(v.z, ssc[4*c+2], ssh[4*c+2]));
            y[4*c+3] = gelu_exact(fmaf(v.w, ssc[4*c+3], ssh[4*c+3]));
        }
    }
    float acc[H];
    #pragma unroll
    for (int j = 0; j < H; j++) acc[j] = sb[j];
    #pragma unroll
    for (int k = 0; k < H; k++)
        #pragma unroll
        for (int j = 0; j < H; j++) acc[j] = fmaf(y[k], sW[k * H + j], acc[j]);

    if (valid) {
        float4* o = (float4*)(g_h2 + (size_t)n * H);
        #pragma unroll
        for (int c = 0; c < H / 4; c++)
            o[c] = make_float4(acc[4*c], acc[4*c+1], acc[4*c+2], acc[4*c+3]);
    }
    stats_epilogue(acc, valid, g_s2);
}

// ---------------------------------------------------------------------------
// K6: out = gelu(bn2(h2)) @ W3 + b3   (BN2 finalize inline)
// ---------------------------------------------------------------------------
__global__ __launch_bounds__(256) void k_out(const float* __restrict__ g2,
                                             const float* __restrict__ bt2,
                                             const float* __restrict__ W3,
                                             const float* __restrict__ b3,
                                             float* __restrict__ out,
                                             int N) {
    __shared__ float sW[H * HO];
    __shared__ float sb[HO], ssc[H], ssh[H];
    for (int i = threadIdx.x; i < H * HO; i += blockDim.x) sW[i] = W3[i];
    if (threadIdx.x < HO) sb[threadIdx.x] = b3[threadIdx.x];
    fin_inline(g_s2, g2, bt2, N, ssc, ssh);
    __syncthreads();

    int n = blockIdx.x * blockDim.x + threadIdx.x;
    if (n >= N) return;

    float y[H];
    const float4* hr = (const float4*)(g_h2 + (size_t)n * H);
    #pragma unroll
    for (int c = 0; c < H / 4; c++) {
        float4 v = hr[c];
        y[4*c+0] = gelu_exact(fmaf(v.x, ssc[4*c+0], ssh[4*c+0]));
        y[4*c+1] = gelu_exact(fmaf(v.y, ssc[4*c+1], ssh[4*c+1]));
        y[4*c+2] = gelu_exact(fmaf(v.z, ssc[4*c+2], ssh[4*c+2]));
        y[4*c+3] = gelu_exact(fmaf(v.w, ssc[4*c+3], ssh[4*c+3]));
    }

    float4* orow = (float4*)(out + (size_t)n * HO);
    #pragma unroll
    for (int jb = 0; jb < HO; jb += 32) {
        float acc[32];
        #pragma unroll
        for (int j = 0; j < 32; j++) acc[j] = sb[jb + j];
        #pragma unroll
        for (int k = 0; k < H; k++)
            #pragma unroll
            for (int j = 0; j < 32; j++) acc[j] = fmaf(y[k], sW[k * HO + jb + j], acc[j]);
        #pragma unroll
        for (int c = 0; c < 8; c++)
            orow[jb / 4 + c] = make_float4(acc[4*c], acc[4*c+1], acc[4*c+2], acc[4*c+3]);
    }
}

// ---------------------------------------------------------------------------
extern "C" void kernel_launch(void* const* d_in, const int* in_sizes, int n_in,
                              void* d_out, int out_size) {
    const float* x    = (const float*)d_in[0];
    const void*  eidx =               d_in[1];
    const float* ea   = (const float*)d_in[2];
    const float* We   = (const float*)d_in[3];
    const float* be   = (const float*)d_in[4];
    const float* W1   = (const float*)d_in[5];
    const float* b1   = (const float*)d_in[6];
    const float* g1   = (const float*)d_in[7];
    const float* bt1  = (const float*)d_in[8];
    const float* W2   = (const float*)d_in[9];
    const float* b2   = (const float*)d_in[10];
    const float* epsp = (const float*)d_in[11];
    const float* g2   = (const float*)d_in[12];
    const float* bt2  = (const float*)d_in[13];
    const float* W3   = (const float*)d_in[14];
    const float* b3   = (const float*)d_in[15];
    float* out = (float*)d_out;

    int N = in_sizes[0] / NF;
    int E = in_sizes[2] / 8;
    int n4 = N * NF / 4;
    int nb = (N + 255) / 256;

    int e1 = E / 3, e2 = 2 * (E / 3);

    k_pre  <<<(n4 + 255) / 256, 256>>>((const int*)eidx, n4);
    // 4 threads per edge
    k_edge <<<((e1) * 4 + 255) / 256, 256>>>(x, eidx, ea, We, be, 0, e1, E);
    k_edge <<<((e2 - e1) * 4 + 255) / 256, 256>>>(x, eidx, ea, We, be, e1, e2, E);
    k_edge <<<((E - e2) * 4 + 255) / 256, 256>>>(x, eidx, ea, We, be, e2, E, E);  // profiled
    k_gemm1<<<nb, 256>>>(x, epsp, W1, b1, N);
    k_gemm2<<<nb, 256>>>(g1, bt1, W2, b2, N);
    k_out  <<<nb, 256>>>(g2, bt2, W3, b3, out, N);
}

// round 6
// speedup vs baseline: 1.9678x; 1.2492x over previous
#include <cuda_runtime.h>
#include <math.h>
#include <stdint.h>

// Problem-fixed sizes: N=100000, E=3200000, NF=16, H=32, HO=64
#define NMAX 100000
#define NF 16
#define H  32
#define HO 64

__device__ float  g_agg[NMAX * NF];   // scatter-sum accumulator (zeroed in k_pre)
__device__ float  g_h1 [NMAX * H];
__device__ float  g_h2 [NMAX * H];
__device__ double g_s1 [2 * H];       // sum[32], sumsq[32]
__device__ double g_s2 [2 * H];
__device__ int    g_is64;

__device__ __forceinline__ float gelu_exact(float v) {
    return 0.5f * v * (1.0f + erff(v * 0.70710678118654752f));
}

// ---------------------------------------------------------------------------
// K0: zero g_agg + stats accumulators; detect edge_index dtype
// ---------------------------------------------------------------------------
__global__ __launch_bounds__(256) void k_pre(const int* __restrict__ eidx32,
                                             int n4 /* N*NF/4 */) {
    int i = blockIdx.x * blockDim.x + threadIdx.x;
    if (i < n4) ((float4*)g_agg)[i] = make_float4(0.f, 0.f, 0.f, 0.f);
    if (blockIdx.x == 0) {
        if (threadIdx.x < 2 * H)       g_s1[threadIdx.x]         = 0.0;
        else if (threadIdx.x < 4 * H)  g_s2[threadIdx.x - 2 * H] = 0.0;
        if (threadIdx.x == 0) {
            int nz = 0;
            #pragma unroll
            for (int k = 0; k < 64; k++) nz |= eidx32[2 * k + 1];
            g_is64 = (nz == 0) ? 1 : 0;
        }
    }
}

// ---------------------------------------------------------------------------
// K1: edge kernel, 4 threads/edge, grid-stride. Lane group c = tid&3 is
// loop-invariant (stride % 4 == 0), so each thread keeps its 32-float weight
// chunk + bias in REGISTERS (loaded once via broadcast LDG) — zero per-edge
// shared-memory traffic. Per edge-thread: idx, 2x ea float4 (broadcast),
// 1 LDG.128 gather, 1 RED.128 scatter.
// ---------------------------------------------------------------------------
__global__ __launch_bounds__(256) void k_edge(const float* __restrict__ x,
                                              const void*  __restrict__ eidx,
                                              const float* __restrict__ ea,
                                              const float* __restrict__ We,
                                              const float* __restrict__ be,
                                              int E) {
    int t = blockIdx.x * blockDim.x + threadIdx.x;
    int c = t & 3;

    // per-thread weight chunk: We[k][4c..4c+4), k = 0..7
    float w[8][4];
    #pragma unroll
    for (int k = 0; k < 8; k++) {
        float4 wv = __ldg((const float4*)(We + k * 16) + c);
        w[k][0] = wv.x; w[k][1] = wv.y; w[k][2] = wv.z; w[k][3] = wv.w;
    }
    float4 bv = __ldg(((const float4*)be) + c);
    int is64 = g_is64;

    int total  = E * 4;
    int stride = gridDim.x * blockDim.x;   // multiple of 4

    for (int gt = t; gt < total; gt += stride) {
        int e = gt >> 2;

        int src, dst;
        if (is64) {
            src = ((const int2*)eidx)[e].x;
            dst = ((const int2*)eidx)[e + E].x;
        } else {
            const int* p32 = (const int*)eidx;
            src = p32[e]; dst = p32[e + E];
        }

        const float4* ear = (const float4*)(ea + (size_t)e * 8);
        float4 a0 = __ldg(ear);
        float4 a1 = __ldg(ear + 1);
        float av[8] = {a0.x, a0.y, a0.z, a0.w, a1.x, a1.y, a1.z, a1.w};

        float m0 = bv.x, m1 = bv.y, m2 = bv.z, m3 = bv.w;
        #pragma unroll
        for (int k = 0; k < 8; k++) {
            m0 = fmaf(av[k], w[k][0], m0);
            m1 = fmaf(av[k], w[k][1], m1);
            m2 = fmaf(av[k], w[k][2], m2);
            m3 = fmaf(av[k], w[k][3], m3);
        }

        float4 xv = __ldg((const float4*)(x + (size_t)src * 16) + c);
        float4 r;
        r.x = fmaxf(xv.x + m0, 0.0f);
        r.y = fmaxf(xv.y + m1, 0.0f);
        r.z = fmaxf(xv.z + m2, 0.0f);
        r.w = fmaxf(xv.w + m3, 0.0f);
        atomicAdd((float4*)(g_agg + (size_t)dst * 16) + c, r);
    }
}

// ---------------------------------------------------------------------------
// stats epilogue: smem transpose (conflict-free), then double atomics
// ---------------------------------------------------------------------------
__device__ __forceinline__ void stats_epilogue(const float* acc, bool valid,
                                               double* sums) {
    __shared__ float tr[8][32][33];
    __shared__ float shs[8][32], shq[8][32];
    int lane = threadIdx.x & 31;
    int wid  = threadIdx.x >> 5;
    #pragma unroll
    for (int j = 0; j < H; j++) tr[wid][j][lane] = valid ? acc[j] : 0.0f;
    __syncwarp();
    float s = 0.0f, q = 0.0f;
    #pragma unroll
    for (int k = 0; k < 32; k++) {
        float v = tr[wid][lane][k];
        s += v; q = fmaf(v, v, q);
    }
    shs[wid][lane] = s; shq[wid][lane] = q;
    __syncthreads();
    if (wid == 0) {
        float ts = 0.0f, tq = 0.0f;
        #pragma unroll
        for (int w = 0; w < 8; w++) { ts += shs[w][lane]; tq += shq[w][lane]; }
        atomicAdd(&sums[lane],     (double)ts);
        atomicAdd(&sums[H + lane], (double)tq);
    }
}

// ---------------------------------------------------------------------------
// BN finalize inline (per-block, threads 0..31 write smem scale/shift)
// ---------------------------------------------------------------------------
__device__ __forceinline__ void fin_inline(const double* __restrict__ sums,
                                           const float* __restrict__ gamma,
                                           const float* __restrict__ beta,
                                           int N, float* ssc, float* ssh) {
    if (threadIdx.x < H) {
        int f = threadIdx.x;
        double mean = sums[f] / (double)N;
        double var  = sums[H + f] / (double)N - mean * mean;
        double inv  = 1.0 / sqrt(var + 1e-5);
        ssc[f] = (float)((double)gamma[f] * inv);
        ssh[f] = (float)((double)beta[f] - mean * (double)gamma[f] * inv);
    }
}

// ---------------------------------------------------------------------------
// K2: h1 = ((1+eps)*x + agg) @ W1 + b1   (+ fused BN1 stats)
// ---------------------------------------------------------------------------
__global__ __launch_bounds__(256) void k_gemm1(const float* __restrict__ x,
                                               const float* __restrict__ epsp,
                                               const float* __restrict__ W1,
                                               const float* __restrict__ b1,
                                               int N) {
    __shared__ float sW[NF * H];
    __shared__ float sb[H];
    for (int i = threadIdx.x; i < NF * H; i += blockDim.x) sW[i] = W1[i];
    if (threadIdx.x < H) sb[threadIdx.x] = b1[threadIdx.x];
    __syncthreads();

    int n = blockIdx.x * blockDim.x + threadIdx.x;
    bool valid = n < N;
    float sc = 1.0f + epsp[0];

    float a[NF];
    #pragma unroll
    for (int k = 0; k < NF; k++) a[k] = 0.0f;
    if (valid) {
        const float4* ar = (const float4*)(g_agg + (size_t)n * NF);
        const float4* xr = (const float4*)(x     + (size_t)n * NF);
        #pragma unroll
        for (int c = 0; c < 4; c++) {
            float4 v = ar[c];
            float4 xv = xr[c];
            a[4*c+0] = fmaf(sc, xv.x, v.x);
            a[4*c+1] = fmaf(sc, xv.y, v.y);
            a[4*c+2] = fmaf(sc, xv.z, v.z);
            a[4*c+3] = fmaf(sc, xv.w, v.w);
        }
    }
    float acc[H];
    #pragma unroll
    for (int j = 0; j < H; j++) acc[j] = sb[j];
    #pragma unroll
    for (int k = 0; k < NF; k++)
        #pragma unroll
        for (int j = 0; j < H; j++) acc[j] = fmaf(a[k], sW[k * H + j], acc[j]);

    if (valid) {
        float4* hr = (float4*)(g_h1 + (size_t)n * H);
        #pragma unroll
        for (int c = 0; c < H / 4; c++)
            hr[c] = make_float4(acc[4*c], acc[4*c+1], acc[4*c+2], acc[4*c+3]);
    }
    stats_epilogue(acc, valid, g_s1);
}

// ---------------------------------------------------------------------------
// K3: h2 = gelu(bn1(h1)) @ W2 + b2   (BN1 finalize inline, + fused BN2 stats)
// ---------------------------------------------------------------------------
__global__ __launch_bounds__(256) void k_gemm2(const float* __restrict__ g1,
                                               const float* __restrict__ bt1,
                                               const float* __restrict__ W2,
                                               const float* __restrict__ b2,
                                               int N) {
    __shared__ float sW[H * H];
    __shared__ float sb[H], ssc[H], ssh[H];
    for (int i = threadIdx.x; i < H * H; i += blockDim.x) sW[i] = W2[i];
    if (threadIdx.x < H) sb[threadIdx.x] = b2[threadIdx.x];
    fin_inline(g_s1, g1, bt1, N, ssc, ssh);
    __syncthreads();

    int n = blockIdx.x * blockDim.x + threadIdx.x;
    bool valid = n < N;

    float y[H];
    #pragma unroll
    for (int j = 0; j < H; j++) y[j] = 0.0f;
    if (valid) {
        const float4* hr = (const float4*)(g_h1 + (size_t)n * H);
        #pragma unroll
        for (int c = 0; c < H / 4; c++) {
            float4 v = hr[c];
            y[4*c+0] = gelu_exact(fmaf(v.x, ssc[4*c+0], ssh[4*c+0]));
            y[4*c+1] = gelu_exact(fmaf(v.y, ssc[4*c+1], ssh[4*c+1]));
            y[4*c+2] = gelu_exact(fmaf(v.z, ssc[4*c+2], ssh[4*c+2]));
            y[4*c+3] = gelu_exact(fmaf(v.w, ssc[4*c+3], ssh[4*c+3]));
        }
    }
    float acc[H];
    #pragma unroll
    for (int j = 0; j < H; j++) acc[j] = sb[j];
    #pragma unroll
    for (int k = 0; k < H; k++)
        #pragma unroll
        for (int j = 0; j < H; j++) acc[j] = fmaf(y[k], sW[k * H + j], acc[j]);

    if (valid) {
        float4* o = (float4*)(g_h2 + (size_t)n * H);
        #pragma unroll
        for (int c = 0; c < H / 4; c++)
            o[c] = make_float4(acc[4*c], acc[4*c+1], acc[4*c+2], acc[4*c+3]);
    }
    stats_epilogue(acc, valid, g_s2);
}

// ---------------------------------------------------------------------------
// K4: out = gelu(bn2(h2)) @ W3 + b3   (BN2 finalize inline)
// ---------------------------------------------------------------------------
__global__ __launch_bounds__(256) void k_out(const float* __restrict__ g2,
                                             const float* __restrict__ bt2,
                                             const float* __restrict__ W3,
                                             const float* __restrict__ b3,
                                             float* __restrict__ out,
                                             int N) {
    __shared__ float sW[H * HO];
    __shared__ float sb[HO], ssc[H], ssh[H];
    for (int i = threadIdx.x; i < H * HO; i += blockDim.x) sW[i] = W3[i];
    if (threadIdx.x < HO) sb[threadIdx.x] = b3[threadIdx.x];
    fin_inline(g_s2, g2, bt2, N, ssc, ssh);
    __syncthreads();

    int n = blockIdx.x * blockDim.x + threadIdx.x;
    if (n >= N) return;

    float y[H];
    const float4* hr = (const float4*)(g_h2 + (size_t)n * H);
    #pragma unroll
    for (int c = 0; c < H / 4; c++) {
        float4 v = hr[c];
        y[4*c+0] = gelu_exact(fmaf(v.x, ssc[4*c+0], ssh[4*c+0]));
        y[4*c+1] = gelu_exact(fmaf(v.y, ssc[4*c+1], ssh[4*c+1]));
        y[4*c+2] = gelu_exact(fmaf(v.z, ssc[4*c+2], ssh[4*c+2]));
        y[4*c+3] = gelu_exact(fmaf(v.w, ssc[4*c+3], ssh[4*c+3]));
    }

    float4* orow = (float4*)(out + (size_t)n * HO);
    #pragma unroll
    for (int jb = 0; jb < HO; jb += 32) {
        float acc[32];
        #pragma unroll
        for (int j = 0; j < 32; j++) acc[j] = sb[jb + j];
        #pragma unroll
        for (int k = 0; k < H; k++)
            #pragma unroll
            for (int j = 0; j < 32; j++) acc[j] = fmaf(y[k], sW[k * HO + jb + j], acc[j]);
        #pragma unroll
        for (int c = 0; c < 8; c++)
            orow[jb / 4 + c] = make_float4(acc[4*c], acc[4*c+1], acc[4*c+2], acc[4*c+3]);
    }
}

// ---------------------------------------------------------------------------
extern "C" void kernel_launch(void* const* d_in, const int* in_sizes, int n_in,
                              void* d_out, int out_size) {
    const float* x    = (const float*)d_in[0];
    const void*  eidx =               d_in[1];
    const float* ea   = (const float*)d_in[2];
    const float* We   = (const float*)d_in[3];
    const float* be   = (const float*)d_in[4];
    const float* W1   = (const float*)d_in[5];
    const float* b1   = (const float*)d_in[6];
    const float* g1   = (const float*)d_in[7];
    const float* bt1  = (const float*)d_in[8];
    const float* W2   = (const float*)d_in[9];
    const float* b2   = (const float*)d_in[10];
    const float* epsp = (const float*)d_in[11];
    const float* g2   = (const float*)d_in[12];
    const float* bt2  = (const float*)d_in[13];
    const float* W3   = (const float*)d_in[14];
    const float* b3   = (const float*)d_in[15];
    float* out = (float*)d_out;

    int N = in_sizes[0] / NF;
    int E = in_sizes[2] / 8;
    int n4 = N * NF / 4;
    int nb = (N + 255) / 256;

    k_pre  <<<(n4 + 255) / 256, 256>>>((const int*)eidx, n4);
    k_edge <<<2048, 256>>>(x, eidx, ea, We, be, E);   // grid-stride, 4 thr/edge
    k_gemm1<<<nb, 256>>>(x, epsp, W1, b1, N);
    k_gemm2<<<nb, 256>>>(g1, bt1, W2, b2, N);         // profiled (launch idx 3)
    k_out  <<<nb, 256>>>(g2, bt2, W3, b3, out, N);
}